// round 4
// baseline (speedup 1.0000x reference)
#include <cuda_runtime.h>

#define NB 64
#define TT 25
#define LL 196
#define VOC 32000
#define EMB 512
#define PROJD 1024
#define DEC 1024
#define G4 4096
#define NSTEP 24
#define KX0 1536
#define KS 8

// ---------------- device state (no allocations allowed) ----------------
__device__ float d_x0[NB * KX0];
__device__ float d_hbuf[3][NB * DEC];
__device__ float d_cbuf[3][NB * DEC];
__device__ float d_ctx[NB * PROJD];
__device__ float d_gpart[KS][NB * G4];
__device__ float d_att[NB * LL];
__device__ float d_hlast[NSTEP * NB * DEC];

__device__ __forceinline__ float sigmf(float x) { return 1.0f / (1.0f + expf(-x)); }

// ---------------- init: h, c, ctx from inputs ----------------
__global__ void init_state(const float* __restrict__ ih, const float* __restrict__ ic,
                           const float* __restrict__ ictx) {
    int idx = blockIdx.x * blockDim.x + threadIdx.x;
    if (idx < 3 * NB * DEC) {
        int l = idx / (NB * DEC);
        int r = idx % (NB * DEC);
        int d = r % DEC;
        d_hbuf[l][r] = ih[l * DEC + d];
        d_cbuf[l][r] = ic[l * DEC + d];
    }
    if (idx < NB * PROJD) d_ctx[idx] = ictx[idx % PROJD];
}

// ---------------- t=0 output plane ----------------
__global__ void out0_kernel(float* __restrict__ out) {
    int idx = blockIdx.x * blockDim.x + threadIdx.x;
    if (idx < NB * VOC) {
        int n = idx / VOC, v = idx % VOC;
        out[(long)n * TT * VOC + v] = (v == 1) ? 10000.0f : 0.0f;
    }
}

// ---------------- build x0 = [emb(tok) | ctx] ----------------
__global__ void embed_kernel(const int* __restrict__ captions, const float* __restrict__ emb,
                             int step) {
    int idx = blockIdx.x * blockDim.x + threadIdx.x;
    if (idx >= NB * KX0) return;
    int n = idx / KX0, k = idx % KX0;
    if (k < EMB) {
        int tok = (step == 0) ? 1 : captions[n * TT + step];
        d_x0[idx] = emb[(long)tok * EMB + k];
    } else {
        d_x0[idx] = d_ctx[n * PROJD + (k - EMB)];
    }
}

// ---------------- LSTM GEMM: partial g = x@Wih^T + h@Whh^T (split-K) ----------------
// grid (G4/64, KS), block 64 threads, each thread 8x8 accumulators.
__global__ void lstm_gemm(int layer, const float* __restrict__ Wih,
                          const float* __restrict__ Whh, int Kx) {
    const float* A = (layer == 0) ? d_x0 : d_hbuf[layer - 1];
    const float* H = d_hbuf[layer];
    int bn = blockIdx.x;
    int split = blockIdx.y;
    int Ktot = Kx + DEC;
    int Kc = Ktot / KS;
    int kbeg = split * Kc, kend = kbeg + Kc;

    __shared__ __align__(16) float As[8][72];
    __shared__ __align__(16) float Bs[8][72];
    int t = threadIdx.x;
    int tx = t & 7, ty = t >> 3;

    float acc[8][8];
#pragma unroll
    for (int i = 0; i < 8; i++)
#pragma unroll
        for (int j = 0; j < 8; j++) acc[i][j] = 0.0f;

    for (int k0 = kbeg; k0 < kend; k0 += 8) {
        const float* Ap;
        const float* Bp;
        int ld, kl;
        if (k0 < Kx) { Ap = A; Bp = Wih; ld = Kx; kl = k0; }
        else         { Ap = H; Bp = Whh; ld = DEC; kl = k0 - Kx; }

        float4 av0 = *(const float4*)(Ap + (long)t * ld + kl);
        float4 av1 = *(const float4*)(Ap + (long)t * ld + kl + 4);
        float4 bv0 = *(const float4*)(Bp + (long)(bn * 64 + t) * ld + kl);
        float4 bv1 = *(const float4*)(Bp + (long)(bn * 64 + t) * ld + kl + 4);

        As[0][t] = av0.x; As[1][t] = av0.y; As[2][t] = av0.z; As[3][t] = av0.w;
        As[4][t] = av1.x; As[5][t] = av1.y; As[6][t] = av1.z; As[7][t] = av1.w;
        Bs[0][t] = bv0.x; Bs[1][t] = bv0.y; Bs[2][t] = bv0.z; Bs[3][t] = bv0.w;
        Bs[4][t] = bv1.x; Bs[5][t] = bv1.y; Bs[6][t] = bv1.z; Bs[7][t] = bv1.w;
        __syncthreads();

#pragma unroll
        for (int kk = 0; kk < 8; kk++) {
            float4 a0 = *(const float4*)&As[kk][ty * 8];
            float4 a1 = *(const float4*)&As[kk][ty * 8 + 4];
            float4 b0 = *(const float4*)&Bs[kk][tx * 8];
            float4 b1 = *(const float4*)&Bs[kk][tx * 8 + 4];
            float am[8] = {a0.x, a0.y, a0.z, a0.w, a1.x, a1.y, a1.z, a1.w};
            float bm[8] = {b0.x, b0.y, b0.z, b0.w, b1.x, b1.y, b1.z, b1.w};
#pragma unroll
            for (int i = 0; i < 8; i++)
#pragma unroll
                for (int j = 0; j < 8; j++) acc[i][j] += am[i] * bm[j];
        }
        __syncthreads();
    }

    float* gp = d_gpart[split];
#pragma unroll
    for (int i = 0; i < 8; i++) {
        int m = ty * 8 + i;
        float* row = gp + (long)m * G4 + bn * 64 + tx * 8;
        *(float4*)row = make_float4(acc[i][0], acc[i][1], acc[i][2], acc[i][3]);
        *(float4*)(row + 4) = make_float4(acc[i][4], acc[i][5], acc[i][6], acc[i][7]);
    }
}

// ---------------- gates: reduce split-K partials + biases, LSTM nonlinearity ----------------
__global__ void gate_kernel(int layer, const float* __restrict__ bih,
                            const float* __restrict__ bhh, int step) {
    int idx = blockIdx.x * blockDim.x + threadIdx.x;
    if (idx >= NB * DEC) return;
    int n = idx / DEC, j = idx % DEC;
    float gv[4];
#pragma unroll
    for (int q = 0; q < 4; q++) {
        int jj = q * DEC + j;
        float v = bih[jj] + bhh[jj];
#pragma unroll
        for (int s = 0; s < KS; s++) v += d_gpart[s][(long)n * G4 + jj];
        gv[q] = v;
    }
    float i_ = sigmf(gv[0]);
    float f_ = sigmf(gv[1]);
    float g_ = tanhf(gv[2]);
    float o_ = sigmf(gv[3]);
    float c2 = f_ * d_cbuf[layer][idx] + i_ * g_;
    float h2 = o_ * tanhf(c2);
    d_cbuf[layer][idx] = c2;
    d_hbuf[layer][idx] = h2;
    if (layer == 2) d_hlast[(long)step * NB * DEC + idx] = h2;
}

// ---------------- attention: energy = keys . h_last ----------------
// grid (NB, 25), 256 threads, one warp per l-row
__global__ void energy_kernel(const float* __restrict__ keys) {
    int n = blockIdx.x;
    int l = blockIdx.y * 8 + (threadIdx.x >> 5);
    int lane = threadIdx.x & 31;
    __shared__ float hs[DEC];
    for (int k = threadIdx.x; k < DEC; k += 256) hs[k] = d_hbuf[2][n * DEC + k];
    __syncthreads();
    if (l >= LL) return;
    const float* kr = keys + ((long)n * LL + l) * DEC;
    float s = 0.0f;
    for (int k = lane; k < DEC; k += 32) s += kr[k] * hs[k];
#pragma unroll
    for (int o = 16; o; o >>= 1) s += __shfl_xor_sync(0xffffffffu, s, o);
    if (lane == 0) d_att[n * LL + l] = s;
}

// ---------------- softmax over L=196 ----------------
__global__ void softmax_kernel() {
    int n = blockIdx.x;
    int t = threadIdx.x;
    __shared__ float red[16];
    float v = (t < LL) ? d_att[n * LL + t] : -3.4e38f;
    float m = v;
#pragma unroll
    for (int o = 16; o; o >>= 1) m = fmaxf(m, __shfl_xor_sync(0xffffffffu, m, o));
    if ((t & 31) == 0) red[t >> 5] = m;
    __syncthreads();
    if (t < 8) {
        float mm = red[t];
#pragma unroll
        for (int o = 4; o; o >>= 1) mm = fmaxf(mm, __shfl_xor_sync(0xffu, mm, o));
        if (t == 0) red[0] = mm;
    }
    __syncthreads();
    float gm = red[0];
    float ex = (t < LL) ? expf(v - gm) : 0.0f;
    float s = ex;
#pragma unroll
    for (int o = 16; o; o >>= 1) s += __shfl_xor_sync(0xffffffffu, s, o);
    if ((t & 31) == 0) red[8 + (t >> 5)] = s;
    __syncthreads();
    if (t < 8) {
        float ss = red[8 + t];
#pragma unroll
        for (int o = 4; o; o >>= 1) ss += __shfl_xor_sync(0xffu, ss, o);
        if (t == 0) red[8] = ss;
    }
    __syncthreads();
    if (t < LL) d_att[n * LL + t] = ex / red[8];
}

// ---------------- ctx = attn . values ----------------
// grid (NB, 4), 256 threads
__global__ void ctx_kernel(const float* __restrict__ values) {
    int n = blockIdx.x;
    int p = blockIdx.y * 256 + threadIdx.x;
    __shared__ float at[LL];
    for (int l = threadIdx.x; l < LL; l += 256) at[l] = d_att[n * LL + l];
    __syncthreads();
    const float* vp = values + (long)n * LL * PROJD + p;
    float acc = 0.0f;
#pragma unroll 4
    for (int l = 0; l < LL; l++) acc += at[l] * vp[(long)l * PROJD];
    d_ctx[n * PROJD + p] = acc;
}

// ---------------- deferred output projection: [1536 x 32000 x 1024] ----------------
// grid (VOC/128, NSTEP), 128 threads, 8x8 acc/thread
__global__ __launch_bounds__(128) void proj_kernel(const float* __restrict__ W,
                                                   const float* __restrict__ bias,
                                                   float* __restrict__ out) {
    int bn = blockIdx.x;  // 0..249  (128 vocab cols each)
    int bm = blockIdx.y;  // 0..23   (step; 64 batch rows)
    __shared__ __align__(16) float As[8][72];
    __shared__ __align__(16) float Bs[8][136];
    int t = threadIdx.x;
    int tx = t & 15, ty = t >> 4;

    float acc[8][8];
#pragma unroll
    for (int i = 0; i < 8; i++)
#pragma unroll
        for (int j = 0; j < 8; j++) acc[i][j] = 0.0f;

    const float* Ab = d_hlast + (long)bm * NB * DEC;
    const float* Bb = W + (long)(bn * 128) * DEC;
    int ar = t >> 1, ah = (t & 1) * 4;

    for (int k0 = 0; k0 < DEC; k0 += 8) {
        float4 av = *(const float4*)(Ab + (long)ar * DEC + k0 + ah);
        float4 bv0 = *(const float4*)(Bb + (long)t * DEC + k0);
        float4 bv1 = *(const float4*)(Bb + (long)t * DEC + k0 + 4);
        As[ah + 0][ar] = av.x; As[ah + 1][ar] = av.y;
        As[ah + 2][ar] = av.z; As[ah + 3][ar] = av.w;
        Bs[0][t] = bv0.x; Bs[1][t] = bv0.y; Bs[2][t] = bv0.z; Bs[3][t] = bv0.w;
        Bs[4][t] = bv1.x; Bs[5][t] = bv1.y; Bs[6][t] = bv1.z; Bs[7][t] = bv1.w;
        __syncthreads();
#pragma unroll
        for (int kk = 0; kk < 8; kk++) {
            float4 a0 = *(const float4*)&As[kk][ty * 8];
            float4 a1 = *(const float4*)&As[kk][ty * 8 + 4];
            float4 b0 = *(const float4*)&Bs[kk][tx * 8];
            float4 b1 = *(const float4*)&Bs[kk][tx * 8 + 4];
            float am[8] = {a0.x, a0.y, a0.z, a0.w, a1.x, a1.y, a1.z, a1.w};
            float bm_[8] = {b0.x, b0.y, b0.z, b0.w, b1.x, b1.y, b1.z, b1.w};
#pragma unroll
            for (int i = 0; i < 8; i++)
#pragma unroll
                for (int j = 0; j < 8; j++) acc[i][j] += am[i] * bm_[j];
        }
        __syncthreads();
    }

    int v0 = bn * 128 + tx * 8;
    float b8[8];
#pragma unroll
    for (int j = 0; j < 8; j++) b8[j] = bias[v0 + j];
#pragma unroll
    for (int i = 0; i < 8; i++) {
        int m = ty * 8 + i;  // batch index
        float* orow = out + ((long)m * TT + bm + 1) * VOC + v0;
        *(float4*)orow = make_float4(acc[i][0] + b8[0], acc[i][1] + b8[1],
                                     acc[i][2] + b8[2], acc[i][3] + b8[3]);
        *(float4*)(orow + 4) = make_float4(acc[i][4] + b8[4], acc[i][5] + b8[5],
                                           acc[i][6] + b8[6], acc[i][7] + b8[7]);
    }
}

// ---------------- launch ----------------
extern "C" void kernel_launch(void* const* d_in, const int* in_sizes, int n_in,
                              void* d_out, int out_size) {
    // input order: keys, values, features, captions, length, emb_table, W_ih0, W_hh0,
    // b_ih0, b_hh0, W_ih_r, W_hh_r, b_ih_r, b_hh_r, out_W, out_b, init_h, init_c, init_ctx
    // Defensive: if the scalar `length` was dropped by the harness, shift indices >= 5.
    int sh = (n_in >= 19) ? 0 : 1;
    const float* keys     = (const float*)d_in[0];
    const float* values   = (const float*)d_in[1];
    const int*   captions = (const int*)d_in[3];
    const float* emb      = (const float*)d_in[5 - sh];
    const float* W_ih0    = (const float*)d_in[6 - sh];
    const float* W_hh0    = (const float*)d_in[7 - sh];
    const float* b_ih0    = (const float*)d_in[8 - sh];
    const float* b_hh0    = (const float*)d_in[9 - sh];
    const float* W_ih_r   = (const float*)d_in[10 - sh];
    const float* W_hh_r   = (const float*)d_in[11 - sh];
    const float* b_ih_r   = (const float*)d_in[12 - sh];
    const float* b_hh_r   = (const float*)d_in[13 - sh];
    const float* out_W    = (const float*)d_in[14 - sh];
    const float* out_b    = (const float*)d_in[15 - sh];
    const float* init_h   = (const float*)d_in[16 - sh];
    const float* init_c   = (const float*)d_in[17 - sh];
    const float* init_ctx = (const float*)d_in[18 - sh];
    float* out = (float*)d_out;

    init_state<<<768, 256>>>(init_h, init_c, init_ctx);
    out0_kernel<<<(NB * VOC + 255) / 256, 256>>>(out);

    for (int s = 0; s < NSTEP; s++) {
        embed_kernel<<<(NB * KX0 + 255) / 256, 256>>>(captions, emb, s);

        lstm_gemm<<<dim3(G4 / 64, KS), 64>>>(0, W_ih0, W_hh0, KX0);
        gate_kernel<<<(NB * DEC + 255) / 256, 256>>>(0, b_ih0, b_hh0, s);

        lstm_gemm<<<dim3(G4 / 64, KS), 64>>>(1, W_ih_r, W_hh_r, DEC);
        gate_kernel<<<(NB * DEC + 255) / 256, 256>>>(1, b_ih_r, b_hh_r, s);

        lstm_gemm<<<dim3(G4 / 64, KS), 64>>>(2, W_ih_r + (long)G4 * DEC,
                                             W_hh_r + (long)G4 * DEC, DEC);
        gate_kernel<<<(NB * DEC + 255) / 256, 256>>>(2, b_ih_r + G4, b_hh_r + G4, s);

        energy_kernel<<<dim3(NB, 25), 256>>>(keys);
        softmax_kernel<<<NB, 256>>>();
        ctx_kernel<<<dim3(NB, 4), 256>>>(values);
    }

    proj_kernel<<<dim3(VOC / 128, NSTEP), 128>>>(out_W, out_b, out);
}

// round 5
// speedup vs baseline: 1.1704x; 1.1704x over previous
#include <cuda_runtime.h>

#define NB 64
#define TT 25
#define LL 196
#define VOC 32000
#define EMB 512
#define PROJD 1024
#define DEC 1024
#define G4 4096
#define NSTEP 24
#define KX0 1536
#define KS 16

// ---------------- device state (no allocations allowed) ----------------
__device__ float d_x0[NB * KX0];
__device__ float d_hbuf[3][NB * DEC];
__device__ float d_cbuf[3][NB * DEC];
__device__ float d_ctx[NB * PROJD];
__device__ float d_gpart[KS][NB * G4];
__device__ float d_att[NB * LL];
__device__ float d_hlast[NSTEP * NB * DEC];

__device__ __forceinline__ float sigmf(float x) { return 1.0f / (1.0f + expf(-x)); }

// ---------------- packed f32x2 helpers (FFMA2: 2x fp32 rate on sm_103a) ----------------
__device__ __forceinline__ unsigned long long dup2(float x) {
    unsigned long long r;
    asm("mov.b64 %0, {%1, %1};" : "=l"(r) : "f"(x));
    return r;
}
__device__ __forceinline__ void ffma2(unsigned long long& acc, unsigned long long a,
                                      unsigned long long b) {
    asm("fma.rn.f32x2 %0, %1, %2, %0;" : "+l"(acc) : "l"(a), "l"(b));
}
__device__ __forceinline__ float2 unpack2(unsigned long long v) {
    float2 r;
    asm("mov.b64 {%0, %1}, %2;" : "=f"(r.x), "=f"(r.y) : "l"(v));
    return r;
}

// ---------------- init: h, c, ctx from inputs ----------------
__global__ void init_state(const float* __restrict__ ih, const float* __restrict__ ic,
                           const float* __restrict__ ictx) {
    int idx = blockIdx.x * blockDim.x + threadIdx.x;
    if (idx < 3 * NB * DEC) {
        int l = idx / (NB * DEC);
        int r = idx % (NB * DEC);
        int d = r % DEC;
        d_hbuf[l][r] = ih[l * DEC + d];
        d_cbuf[l][r] = ic[l * DEC + d];
    }
    if (idx < NB * PROJD) d_ctx[idx] = ictx[idx % PROJD];
}

// ---------------- t=0 output plane ----------------
__global__ void out0_kernel(float* __restrict__ out) {
    int idx = blockIdx.x * blockDim.x + threadIdx.x;
    if (idx < NB * VOC) {
        int n = idx / VOC, v = idx % VOC;
        out[(long)n * TT * VOC + v] = (v == 1) ? 10000.0f : 0.0f;
    }
}

// ---------------- build x0 = [emb(tok) | ctx]  (only used for step 0) ----------------
__global__ void embed_kernel(const int* __restrict__ captions, const float* __restrict__ emb,
                             int step) {
    int idx = blockIdx.x * blockDim.x + threadIdx.x;
    if (idx >= NB * KX0) return;
    int n = idx / KX0, k = idx % KX0;
    if (k < EMB) {
        int tok = (step == 0) ? 1 : captions[n * TT + step];
        d_x0[idx] = emb[(long)tok * EMB + k];
    } else {
        d_x0[idx] = d_ctx[n * PROJD + (k - EMB)];
    }
}

// ---------------- LSTM GEMM tile loader (handles x|h split in K) ----------------
__device__ __forceinline__ void lstm_ldk(const float* __restrict__ A, const float* __restrict__ H,
                                         const float* __restrict__ Wih,
                                         const float* __restrict__ Whh, int Kx, int k0, int t,
                                         int bn, float4& a0, float4& a1, float4& b0, float4& b1) {
    const float *Ap, *Bp;
    int ld, kl;
    if (k0 < Kx) { Ap = A; Bp = Wih; ld = Kx; kl = k0; }
    else         { Ap = H; Bp = Whh; ld = DEC; kl = k0 - Kx; }
    const float* ar = Ap + (long)t * ld + kl;
    a0 = *(const float4*)ar;
    a1 = *(const float4*)(ar + 4);
    const float* br = Bp + (long)(bn * 64 + t) * ld + kl;
    b0 = *(const float4*)br;
    b1 = *(const float4*)(br + 4);
}

// ---------------- LSTM GEMM: partial g = x@Wih^T + h@Whh^T (split-K=16) ----------------
// grid (G4/64, KS), 64 threads, 8x8 outputs/thread, FFMA2, double-buffered smem.
__global__ __launch_bounds__(64, 8) void lstm_gemm(int layer, const float* __restrict__ Wih,
                                                   const float* __restrict__ Whh, int Kx) {
    const float* A = (layer == 0) ? d_x0 : d_hbuf[layer - 1];
    const float* H = d_hbuf[layer];
    int bn = blockIdx.x;
    int split = blockIdx.y;
    int Ktot = Kx + DEC;
    int Kc = Ktot / KS;
    int kbeg = split * Kc, kend = kbeg + Kc;

    __shared__ __align__(16) float As[2][8][72];
    __shared__ __align__(16) float Bs[2][8][72];
    int t = threadIdx.x;
    int tx = t & 7, ty = t >> 3;

    unsigned long long acc[8][4];
#pragma unroll
    for (int i = 0; i < 8; i++)
#pragma unroll
        for (int j = 0; j < 4; j++) acc[i][j] = 0ull;

    float4 av0, av1, bv0, bv1;
    lstm_ldk(A, H, Wih, Whh, Kx, kbeg, t, bn, av0, av1, bv0, bv1);

    int buf = 0;
    for (int k0 = kbeg; k0 < kend; k0 += 8) {
        As[buf][0][t] = av0.x; As[buf][1][t] = av0.y; As[buf][2][t] = av0.z; As[buf][3][t] = av0.w;
        As[buf][4][t] = av1.x; As[buf][5][t] = av1.y; As[buf][6][t] = av1.z; As[buf][7][t] = av1.w;
        Bs[buf][0][t] = bv0.x; Bs[buf][1][t] = bv0.y; Bs[buf][2][t] = bv0.z; Bs[buf][3][t] = bv0.w;
        Bs[buf][4][t] = bv1.x; Bs[buf][5][t] = bv1.y; Bs[buf][6][t] = bv1.z; Bs[buf][7][t] = bv1.w;
        __syncthreads();

        if (k0 + 8 < kend)
            lstm_ldk(A, H, Wih, Whh, Kx, k0 + 8, t, bn, av0, av1, bv0, bv1);

#pragma unroll
        for (int kk = 0; kk < 8; kk++) {
            float4 a0 = *(const float4*)&As[buf][kk][ty * 8];
            float4 a1 = *(const float4*)&As[buf][kk][ty * 8 + 4];
            unsigned long long a2[8] = {dup2(a0.x), dup2(a0.y), dup2(a0.z), dup2(a0.w),
                                        dup2(a1.x), dup2(a1.y), dup2(a1.z), dup2(a1.w)};
            const unsigned long long* bp = (const unsigned long long*)&Bs[buf][kk][tx * 8];
            unsigned long long bm0 = bp[0], bm1 = bp[1], bm2 = bp[2], bm3 = bp[3];
#pragma unroll
            for (int i = 0; i < 8; i++) {
                ffma2(acc[i][0], a2[i], bm0);
                ffma2(acc[i][1], a2[i], bm1);
                ffma2(acc[i][2], a2[i], bm2);
                ffma2(acc[i][3], a2[i], bm3);
            }
        }
        buf ^= 1;
    }

    float* gp = d_gpart[split];
#pragma unroll
    for (int i = 0; i < 8; i++) {
        int m = ty * 8 + i;
        float2 p0 = unpack2(acc[i][0]), p1 = unpack2(acc[i][1]);
        float2 p2 = unpack2(acc[i][2]), p3 = unpack2(acc[i][3]);
        float* row = gp + (long)m * G4 + bn * 64 + tx * 8;
        *(float4*)row = make_float4(p0.x, p0.y, p1.x, p1.y);
        *(float4*)(row + 4) = make_float4(p2.x, p2.y, p3.x, p3.y);
    }
}

// ---------------- gates: reduce split-K partials + biases, LSTM nonlinearity ----------------
__global__ void gate_kernel(int layer, const float* __restrict__ bih,
                            const float* __restrict__ bhh, int step) {
    int idx = blockIdx.x * blockDim.x + threadIdx.x;
    if (idx >= NB * DEC) return;
    int n = idx / DEC, j = idx % DEC;
    float gv[4];
#pragma unroll
    for (int q = 0; q < 4; q++) {
        int jj = q * DEC + j;
        float v = bih[jj] + bhh[jj];
#pragma unroll
        for (int s = 0; s < KS; s++) v += d_gpart[s][(long)n * G4 + jj];
        gv[q] = v;
    }
    float i_ = sigmf(gv[0]);
    float f_ = sigmf(gv[1]);
    float g_ = tanhf(gv[2]);
    float o_ = sigmf(gv[3]);
    float c2 = f_ * d_cbuf[layer][idx] + i_ * g_;
    float h2 = o_ * tanhf(c2);
    d_cbuf[layer][idx] = c2;
    d_hbuf[layer][idx] = h2;
    if (layer == 2) d_hlast[(long)step * NB * DEC + idx] = h2;
}

// ---------------- attention: energy = keys . h_last ----------------
__global__ void energy_kernel(const float* __restrict__ keys) {
    int n = blockIdx.x;
    int l = blockIdx.y * 8 + (threadIdx.x >> 5);
    int lane = threadIdx.x & 31;
    __shared__ float hs[DEC];
    for (int k = threadIdx.x; k < DEC; k += 256) hs[k] = d_hbuf[2][n * DEC + k];
    __syncthreads();
    if (l >= LL) return;
    const float* kr = keys + ((long)n * LL + l) * DEC;
    float s = 0.0f;
    for (int k = lane; k < DEC; k += 32) s += kr[k] * hs[k];
#pragma unroll
    for (int o = 16; o; o >>= 1) s += __shfl_xor_sync(0xffffffffu, s, o);
    if (lane == 0) d_att[n * LL + l] = s;
}

// ---------------- softmax over L=196 ----------------
__global__ void softmax_kernel() {
    int n = blockIdx.x;
    int t = threadIdx.x;
    __shared__ float red[16];
    float v = (t < LL) ? d_att[n * LL + t] : -3.4e38f;
    float m = v;
#pragma unroll
    for (int o = 16; o; o >>= 1) m = fmaxf(m, __shfl_xor_sync(0xffffffffu, m, o));
    if ((t & 31) == 0) red[t >> 5] = m;
    __syncthreads();
    if (t < 8) {
        float mm = red[t];
#pragma unroll
        for (int o = 4; o; o >>= 1) mm = fmaxf(mm, __shfl_xor_sync(0xffu, mm, o));
        if (t == 0) red[0] = mm;
    }
    __syncthreads();
    float gm = red[0];
    float ex = (t < LL) ? expf(v - gm) : 0.0f;
    float s = ex;
#pragma unroll
    for (int o = 16; o; o >>= 1) s += __shfl_xor_sync(0xffffffffu, s, o);
    if ((t & 31) == 0) red[8 + (t >> 5)] = s;
    __syncthreads();
    if (t < 8) {
        float ss = red[8 + t];
#pragma unroll
        for (int o = 4; o; o >>= 1) ss += __shfl_xor_sync(0xffu, ss, o);
        if (t == 0) red[8] = ss;
    }
    __syncthreads();
    if (t < LL) d_att[n * LL + t] = ex / red[8];
}

// ---------------- ctx = attn . values, fused with x0 build for next step ----------------
// grid (NB, 4), 256 threads
__global__ void ctx_kernel(const float* __restrict__ values, const int* __restrict__ captions,
                           const float* __restrict__ emb, int next_step) {
    int n = blockIdx.x;
    int p = blockIdx.y * 256 + threadIdx.x;
    __shared__ float at[LL];
    for (int l = threadIdx.x; l < LL; l += 256) at[l] = d_att[n * LL + l];
    __syncthreads();
    const float* vp = values + (long)n * LL * PROJD + p;
    float acc = 0.0f;
#pragma unroll 4
    for (int l = 0; l < LL; l++) acc += at[l] * vp[(long)l * PROJD];
    // ctx feeds only x0[:, EMB:] of the next step — write it there directly
    d_x0[n * KX0 + EMB + p] = acc;
    // one block per n also refreshes the embedding part of x0 for the next token
    if (blockIdx.y == 0) {
        int tok = captions[n * TT + next_step];
        const float* er = emb + (long)tok * EMB;
        for (int k = threadIdx.x; k < EMB; k += 256) d_x0[n * KX0 + k] = er[k];
    }
}

// ---------------- deferred output projection: [1536 x 32000 x 1024] ----------------
// grid (VOC/128, 1536/128), 256 threads, 8x8 outputs/thread, FFMA2, double-buffered.
__global__ __launch_bounds__(256, 2) void proj_kernel(const float* __restrict__ W,
                                                      const float* __restrict__ bias,
                                                      float* __restrict__ out) {
    int bn = blockIdx.x;  // 0..249  (128 vocab cols)
    int bm = blockIdx.y;  // 0..11   (128 M rows = 2 steps x 64 batch)
    __shared__ __align__(16) float As[2][8][136];
    __shared__ __align__(16) float Bs[2][8][136];
    int t = threadIdx.x;
    int tx = t & 15, ty = t >> 4;
    int lrow = t >> 1, koff = (t & 1) * 4;

    const float* Ab = d_hlast + (long)(bm * 128) * DEC;
    const float* Bb = W + (long)(bn * 128) * DEC;

    unsigned long long acc[8][4];
#pragma unroll
    for (int i = 0; i < 8; i++)
#pragma unroll
        for (int j = 0; j < 4; j++) acc[i][j] = 0ull;

    float4 av = *(const float4*)(Ab + (long)lrow * DEC + koff);
    float4 bv = *(const float4*)(Bb + (long)lrow * DEC + koff);

    int buf = 0;
    for (int k0 = 0; k0 < DEC; k0 += 8) {
        As[buf][koff + 0][lrow] = av.x; As[buf][koff + 1][lrow] = av.y;
        As[buf][koff + 2][lrow] = av.z; As[buf][koff + 3][lrow] = av.w;
        Bs[buf][koff + 0][lrow] = bv.x; Bs[buf][koff + 1][lrow] = bv.y;
        Bs[buf][koff + 2][lrow] = bv.z; Bs[buf][koff + 3][lrow] = bv.w;
        __syncthreads();

        if (k0 + 8 < DEC) {
            av = *(const float4*)(Ab + (long)lrow * DEC + k0 + 8 + koff);
            bv = *(const float4*)(Bb + (long)lrow * DEC + k0 + 8 + koff);
        }

#pragma unroll
        for (int kk = 0; kk < 8; kk++) {
            float4 a0 = *(const float4*)&As[buf][kk][ty * 8];
            float4 a1 = *(const float4*)&As[buf][kk][ty * 8 + 4];
            unsigned long long a2[8] = {dup2(a0.x), dup2(a0.y), dup2(a0.z), dup2(a0.w),
                                        dup2(a1.x), dup2(a1.y), dup2(a1.z), dup2(a1.w)};
            const unsigned long long* bp = (const unsigned long long*)&Bs[buf][kk][tx * 8];
            unsigned long long bm0 = bp[0], bm1 = bp[1], bm2 = bp[2], bm3 = bp[3];
#pragma unroll
            for (int i = 0; i < 8; i++) {
                ffma2(acc[i][0], a2[i], bm0);
                ffma2(acc[i][1], a2[i], bm1);
                ffma2(acc[i][2], a2[i], bm2);
                ffma2(acc[i][3], a2[i], bm3);
            }
        }
        buf ^= 1;
    }

    int v0 = bn * 128 + tx * 8;
    float b8[8];
#pragma unroll
    for (int j = 0; j < 8; j++) b8[j] = bias[v0 + j];
#pragma unroll
    for (int i = 0; i < 8; i++) {
        int m = bm * 128 + ty * 8 + i;
        int step = m >> 6, n = m & 63;
        float2 p0 = unpack2(acc[i][0]), p1 = unpack2(acc[i][1]);
        float2 p2 = unpack2(acc[i][2]), p3 = unpack2(acc[i][3]);
        float* orow = out + ((long)n * TT + step + 1) * VOC + v0;
        *(float4*)orow = make_float4(p0.x + b8[0], p0.y + b8[1], p1.x + b8[2], p1.y + b8[3]);
        *(float4*)(orow + 4) = make_float4(p2.x + b8[4], p2.y + b8[5], p3.x + b8[6], p3.y + b8[7]);
    }
}

// ---------------- launch ----------------
extern "C" void kernel_launch(void* const* d_in, const int* in_sizes, int n_in,
                              void* d_out, int out_size) {
    int sh = (n_in >= 19) ? 0 : 1;
    const float* keys     = (const float*)d_in[0];
    const float* values   = (const float*)d_in[1];
    const int*   captions = (const int*)d_in[3];
    const float* emb      = (const float*)d_in[5 - sh];
    const float* W_ih0    = (const float*)d_in[6 - sh];
    const float* W_hh0    = (const float*)d_in[7 - sh];
    const float* b_ih0    = (const float*)d_in[8 - sh];
    const float* b_hh0    = (const float*)d_in[9 - sh];
    const float* W_ih_r   = (const float*)d_in[10 - sh];
    const float* W_hh_r   = (const float*)d_in[11 - sh];
    const float* b_ih_r   = (const float*)d_in[12 - sh];
    const float* b_hh_r   = (const float*)d_in[13 - sh];
    const float* out_W    = (const float*)d_in[14 - sh];
    const float* out_b    = (const float*)d_in[15 - sh];
    const float* init_h   = (const float*)d_in[16 - sh];
    const float* init_c   = (const float*)d_in[17 - sh];
    const float* init_ctx = (const float*)d_in[18 - sh];
    float* out = (float*)d_out;

    init_state<<<768, 256>>>(init_h, init_c, init_ctx);
    out0_kernel<<<(NB * VOC + 255) / 256, 256>>>(out);
    embed_kernel<<<(NB * KX0 + 255) / 256, 256>>>(captions, emb, 0);

    for (int s = 0; s < NSTEP; s++) {
        lstm_gemm<<<dim3(G4 / 64, KS), 64>>>(0, W_ih0, W_hh0, KX0);
        gate_kernel<<<(NB * DEC + 255) / 256, 256>>>(0, b_ih0, b_hh0, s);

        lstm_gemm<<<dim3(G4 / 64, KS), 64>>>(1, W_ih_r, W_hh_r, DEC);
        gate_kernel<<<(NB * DEC + 255) / 256, 256>>>(1, b_ih_r, b_hh_r, s);

        lstm_gemm<<<dim3(G4 / 64, KS), 64>>>(2, W_ih_r + (long)G4 * DEC,
                                             W_hh_r + (long)G4 * DEC, DEC);
        gate_kernel<<<(NB * DEC + 255) / 256, 256>>>(2, b_ih_r + G4, b_hh_r + G4, s);

        energy_kernel<<<dim3(NB, 25), 256>>>(keys);
        softmax_kernel<<<NB, 256>>>();
        // fused: ctx + build x0 for step s+1 (token s+1)
        ctx_kernel<<<dim3(NB, 4), 256>>>(values, captions, emb, s + 1);
    }

    proj_kernel<<<dim3(VOC / 128, NSTEP * NB / 128), 256>>>(out_W, out_b, out);
}

// round 7
// speedup vs baseline: 1.5691x; 1.3406x over previous
#include <cuda_runtime.h>
#include <stdint.h>

#define NB 64
#define TT 25
#define LL 196
#define VOC 32000
#define EMB 512
#define PROJD 1024
#define DEC 1024
#define G4 4096
#define NSTEP 24
#define KX0 1536
#define KSMAX 5

// ---------------- device state (no allocations allowed) ----------------
__device__ float d_x0[NB * KX0];
__device__ float d_hbuf[3][NB * DEC];
__device__ float d_cbuf[3][NB * DEC];
__device__ float d_ctx[NB * PROJD];
__device__ float d_gpart[KSMAX][NB * G4];
__device__ float d_hlast[NSTEP * NB * DEC];

__device__ __forceinline__ float sigmf(float x) { return 1.0f / (1.0f + expf(-x)); }

// ---------------- baseline-ISA async copy helpers ----------------
__device__ __forceinline__ uint32_t smem_u32(const void* p) {
    uint32_t a;
    asm("{ .reg .u64 t; cvta.to.shared.u64 t, %1; cvt.u32.u64 %0, t; }" : "=r"(a) : "l"(p));
    return a;
}
#define CPA16(d, s) asm volatile("cp.async.ca.shared.global [%0], [%1], 16;" :: "r"(d), "l"(s))
#define CP_COMMIT() asm volatile("cp.async.commit_group;" ::: "memory")
#define CP_WAIT1() asm volatile("cp.async.wait_group 1;" ::: "memory")
#define CP_WAIT0() asm volatile("cp.async.wait_group 0;" ::: "memory")

// ---------------- warp-level tf32 MMA (baseline sm_80+ ISA, runs on tensor pipe) ----------------
// C[16x8] += A[16x8] * B[8x8], A row-major, B col-major, fp32 bits read as tf32.
__device__ __forceinline__ void mma16n8k8(float* c, const uint32_t* a, const uint32_t* b) {
    asm volatile(
        "mma.sync.aligned.m16n8k8.row.col.f32.tf32.tf32.f32 "
        "{%0,%1,%2,%3}, {%4,%5,%6,%7}, {%8,%9}, {%0,%1,%2,%3};"
        : "+f"(c[0]), "+f"(c[1]), "+f"(c[2]), "+f"(c[3])
        : "r"(a[0]), "r"(a[1]), "r"(a[2]), "r"(a[3]), "r"(b[0]), "r"(b[1]));
}

// ---------------- init / out0 / embed (step 0 only) ----------------
__global__ void init_state(const float* __restrict__ ih, const float* __restrict__ ic,
                           const float* __restrict__ ictx) {
    int idx = blockIdx.x * blockDim.x + threadIdx.x;
    if (idx < 3 * NB * DEC) {
        int l = idx / (NB * DEC);
        int r = idx % (NB * DEC);
        int d = r % DEC;
        d_hbuf[l][r] = ih[l * DEC + d];
        d_cbuf[l][r] = ic[l * DEC + d];
    }
    if (idx < NB * PROJD) d_ctx[idx] = ictx[idx % PROJD];
}

__global__ void out0_kernel(float* __restrict__ out) {
    int idx = blockIdx.x * blockDim.x + threadIdx.x;
    if (idx < NB * VOC) {
        int n = idx / VOC, v = idx % VOC;
        out[(long)n * TT * VOC + v] = (v == 1) ? 10000.0f : 0.0f;
    }
}

__global__ void embed_kernel(const int* __restrict__ captions, const float* __restrict__ emb,
                             int step) {
    int idx = blockIdx.x * blockDim.x + threadIdx.x;
    if (idx >= NB * KX0) return;
    int n = idx / KX0, k = idx % KX0;
    if (k < EMB) {
        int tok = (step == 0) ? 1 : captions[n * TT + step];
        d_x0[idx] = emb[(long)tok * EMB + k];
    } else {
        d_x0[idx] = d_ctx[n * PROJD + (k - EMB)];
    }
}

// ---------------- LSTM GEMM via mma.sync tf32 ----------------
// g[64 x 4096] = act[64 x Ktot] @ W[4096 x Ktot]^T, split-K (512/CTA).
// grid (32, KS), 256 threads. CTA tile M=64(batch) x N=128(W rows).
// Smem per buf: X 64x36 floats (9216B) + W 128x36 (18432B) = 27648B; double buffered.
#define LS_BUF 27648
#define LS_SMEM (2 * LS_BUF)

__device__ __forceinline__ void lstm_load(uint32_t xs, uint32_t ws, const float* __restrict__ Ba,
                                          const float* __restrict__ Aw, int ld, int kl, int bn,
                                          int tid) {
#pragma unroll
    for (int i = 0; i < 4; i++) {  // W tile: 128 rows x 8 granules
        int gI = tid + i * 256;
        int row = gI >> 3, c = gI & 7;
        CPA16(ws + row * 144 + c * 16, Aw + (long)(bn * 128 + row) * ld + kl + c * 4);
    }
#pragma unroll
    for (int i = 0; i < 2; i++) {  // X tile: 64 rows x 8 granules
        int gI = tid + i * 256;
        int row = gI >> 3, c = gI & 7;
        CPA16(xs + row * 144 + c * 16, Ba + (long)row * ld + kl + c * 4);
    }
}

__global__ __launch_bounds__(256) void lstm_mma(int layer, const float* __restrict__ Wih,
                                                const float* __restrict__ Whh, int Kx) {
    extern __shared__ char smem[];
    uint32_t sb = smem_u32(smem);
    const int tid = threadIdx.x;
    const int w = tid >> 5, lane = tid & 31;
    const int g = lane >> 2, tig = lane & 3;
    const int bn = blockIdx.x, split = blockIdx.y;
    const int kbeg = split * 512;
    const float* Bx = (layer == 0) ? d_x0 : d_hbuf[layer - 1];
    const float* Bh = d_hbuf[layer];

    float acc[4][2][4] = {};

    {  // preload chunk 0
        int k0 = kbeg;
        const float *Aw, *Ba;
        int ld, kl;
        if (k0 < Kx) { Aw = Wih; Ba = Bx; ld = Kx; kl = k0; }
        else         { Aw = Whh; Ba = Bh; ld = DEC; kl = k0 - Kx; }
        lstm_load(sb, sb + 9216, Ba, Aw, ld, kl, bn, tid);
        CP_COMMIT();
    }

    for (int c = 0; c < 16; c++) {
        int b = c & 1;
        __syncthreads();  // compute on buffer b^1 (chunk c-1) fully done before overwrite
        if (c + 1 < 16) {
            int k0 = kbeg + (c + 1) * 32;
            const float *Aw, *Ba;
            int ld, kl;
            if (k0 < Kx) { Aw = Wih; Ba = Bx; ld = Kx; kl = k0; }
            else         { Aw = Whh; Ba = Bh; ld = DEC; kl = k0 - Kx; }
            uint32_t nb = sb + (b ^ 1) * LS_BUF;
            lstm_load(nb, nb + 9216, Ba, Aw, ld, kl, bn, tid);
            CP_COMMIT();
            CP_WAIT1();
        } else {
            CP_WAIT0();
        }
        __syncthreads();

        const float* Xb = (const float*)(smem + b * LS_BUF);
        const float* Wb = (const float*)(smem + b * LS_BUF + 9216);
#pragma unroll
        for (int kk = 0; kk < 4; kk++) {
            int k0 = kk * 8;
            uint32_t a[4][4];
#pragma unroll
            for (int mi = 0; mi < 4; mi++) {
                int r = mi * 16 + g;
                a[mi][0] = __float_as_uint(Xb[r * 36 + k0 + tig]);
                a[mi][1] = __float_as_uint(Xb[(r + 8) * 36 + k0 + tig]);
                a[mi][2] = __float_as_uint(Xb[r * 36 + k0 + tig + 4]);
                a[mi][3] = __float_as_uint(Xb[(r + 8) * 36 + k0 + tig + 4]);
            }
#pragma unroll
            for (int nj = 0; nj < 2; nj++) {
                int n0 = w * 16 + nj * 8;
                uint32_t bb[2];
                bb[0] = __float_as_uint(Wb[(n0 + g) * 36 + k0 + tig]);
                bb[1] = __float_as_uint(Wb[(n0 + g) * 36 + k0 + tig + 4]);
#pragma unroll
                for (int mi = 0; mi < 4; mi++) mma16n8k8(acc[mi][nj], a[mi], bb);
            }
        }
    }

    // epilogue: C[m=batch][n=W row] -> d_gpart[split][m*G4 + n]
    float* gp = d_gpart[split];
#pragma unroll
    for (int mi = 0; mi < 4; mi++) {
#pragma unroll
        for (int nj = 0; nj < 2; nj++) {
            int m = mi * 16 + g;
            int coln = bn * 128 + w * 16 + nj * 8 + tig * 2;
            *(float2*)(gp + (long)m * G4 + coln) = make_float2(acc[mi][nj][0], acc[mi][nj][1]);
            *(float2*)(gp + (long)(m + 8) * G4 + coln) =
                make_float2(acc[mi][nj][2], acc[mi][nj][3]);
        }
    }
}

// ---------------- gates: reduce split-K partials + biases ----------------
__global__ void gate_kernel(int layer, const float* __restrict__ bih,
                            const float* __restrict__ bhh, int ks, int step) {
    int idx = blockIdx.x * blockDim.x + threadIdx.x;
    if (idx >= NB * DEC) return;
    int n = idx / DEC, j = idx % DEC;
    float gv[4];
#pragma unroll
    for (int q = 0; q < 4; q++) {
        int jj = q * DEC + j;
        float v = bih[jj] + bhh[jj];
        for (int s = 0; s < ks; s++) v += d_gpart[s][(long)n * G4 + jj];
        gv[q] = v;
    }
    float i_ = sigmf(gv[0]);
    float f_ = sigmf(gv[1]);
    float g_ = tanhf(gv[2]);
    float o_ = sigmf(gv[3]);
    float c2 = f_ * d_cbuf[layer][idx] + i_ * g_;
    float h2 = o_ * tanhf(c2);
    d_cbuf[layer][idx] = c2;
    d_hbuf[layer][idx] = h2;
    if (layer == 2) d_hlast[(long)step * NB * DEC + idx] = h2;
}

// ---------------- fused attention: energy + softmax + ctx + x0 build ----------------
// grid 64, 256 threads
__global__ void attn_kernel(const float* __restrict__ keys, const float* __restrict__ values,
                            const int* __restrict__ captions, const float* __restrict__ emb,
                            int next_step) {
    int n = blockIdx.x;
    int tid = threadIdx.x;
    int wid = tid >> 5, lane = tid & 31;
    __shared__ float hs[DEC];
    __shared__ float e[LL];
    __shared__ float red[8], red2[8];
    for (int k = tid; k < DEC; k += 256) hs[k] = d_hbuf[2][n * DEC + k];
    __syncthreads();
    for (int r = wid; r < LL; r += 8) {
        const float4* kr = (const float4*)(keys + ((long)n * LL + r) * DEC);
        float s = 0.f;
        for (int k = lane; k < DEC / 4; k += 32) {
            float4 kv = kr[k];
            s += kv.x * hs[k * 4] + kv.y * hs[k * 4 + 1] + kv.z * hs[k * 4 + 2] +
                 kv.w * hs[k * 4 + 3];
        }
#pragma unroll
        for (int o = 16; o; o >>= 1) s += __shfl_xor_sync(0xffffffffu, s, o);
        if (lane == 0) e[r] = s;
    }
    __syncthreads();
    float v = (tid < LL) ? e[tid] : -3.4e38f;
    float m = v;
#pragma unroll
    for (int o = 16; o; o >>= 1) m = fmaxf(m, __shfl_xor_sync(0xffffffffu, m, o));
    if (lane == 0) red[wid] = m;
    __syncthreads();
    if (tid < 8) {
        float mm = red[tid];
#pragma unroll
        for (int o = 4; o; o >>= 1) mm = fmaxf(mm, __shfl_xor_sync(0xffu, mm, o));
        if (tid == 0) red[0] = mm;
    }
    __syncthreads();
    float gm = red[0];
    float ex = (tid < LL) ? expf(v - gm) : 0.f;
    float s = ex;
#pragma unroll
    for (int o = 16; o; o >>= 1) s += __shfl_xor_sync(0xffffffffu, s, o);
    if (lane == 0) red2[wid] = s;
    __syncthreads();
    if (tid < 8) {
        float ss = red2[tid];
#pragma unroll
        for (int o = 4; o; o >>= 1) ss += __shfl_xor_sync(0xffu, ss, o);
        if (tid == 0) red2[0] = ss;
    }
    __syncthreads();
    if (tid < LL) e[tid] = ex / red2[0];
    __syncthreads();
    const float4* vp = (const float4*)(values + (long)n * LL * PROJD) + tid;
    float4 acc = make_float4(0.f, 0.f, 0.f, 0.f);
#pragma unroll 2
    for (int l = 0; l < LL; l++) {
        float w = e[l];
        float4 vv = vp[(long)l * (PROJD / 4)];
        acc.x += w * vv.x; acc.y += w * vv.y; acc.z += w * vv.z; acc.w += w * vv.w;
    }
    ((float4*)(d_x0 + n * KX0 + EMB))[tid] = acc;
    int tok = captions[n * TT + next_step];
    for (int k = tid; k < EMB; k += 256) d_x0[n * KX0 + k] = emb[(long)tok * EMB + k];
}

// ---------------- projection via mma.sync tf32 ----------------
// out[1536 x 32000] = hlast[1536 x 1024] @ out_W[32000 x 1024]^T.
// grid (250, 12), 256 threads. CTA tile M=128(h rows) x N=128(vocab), K=1024 (32 chunks).
// Smem per buf: A 128x36 (18432B) + B 128x36 (18432B) = 36864B; double buffered.
#define PJ_BUF 36864
#define PJ_SMEM (2 * PJ_BUF)

__device__ __forceinline__ void proj_load(uint32_t as, uint32_t bs, const float* __restrict__ W,
                                          int bn, int bm, int k0, int tid) {
#pragma unroll
    for (int i = 0; i < 4; i++) {  // A: hlast rows bm*128..+127
        int gI = tid + i * 256;
        int row = gI >> 3, c = gI & 7;
        CPA16(as + row * 144 + c * 16, d_hlast + (long)(bm * 128 + row) * DEC + k0 + c * 4);
    }
#pragma unroll
    for (int i = 0; i < 4; i++) {  // B: W rows bn*128..+127
        int gI = tid + i * 256;
        int row = gI >> 3, c = gI & 7;
        CPA16(bs + row * 144 + c * 16, W + (long)(bn * 128 + row) * DEC + k0 + c * 4);
    }
}

__global__ __launch_bounds__(256) void proj_mma(const float* __restrict__ W,
                                                const float* __restrict__ bias,
                                                float* __restrict__ out) {
    extern __shared__ char smem[];
    uint32_t sb = smem_u32(smem);
    const int tid = threadIdx.x;
    const int w = tid >> 5, lane = tid & 31;
    const int g = lane >> 2, tig = lane & 3;
    const int wm = w >> 2, wn = w & 3;  // warp tile: rows wm*64, cols wn*32
    const int bn = blockIdx.x, bm = blockIdx.y;

    float acc[4][4][4] = {};

    proj_load(sb, sb + 18432, W, bn, bm, 0, tid);
    CP_COMMIT();

    for (int c = 0; c < 32; c++) {
        int b = c & 1;
        __syncthreads();
        if (c + 1 < 32) {
            uint32_t nb = sb + (b ^ 1) * PJ_BUF;
            proj_load(nb, nb + 18432, W, bn, bm, (c + 1) * 32, tid);
            CP_COMMIT();
            CP_WAIT1();
        } else {
            CP_WAIT0();
        }
        __syncthreads();

        const float* Ab = (const float*)(smem + b * PJ_BUF);
        const float* Bb = (const float*)(smem + b * PJ_BUF + 18432);
#pragma unroll
        for (int kk = 0; kk < 4; kk++) {
            int k0 = kk * 8;
            uint32_t a[4][4];
#pragma unroll
            for (int mi = 0; mi < 4; mi++) {
                int r = wm * 64 + mi * 16 + g;
                a[mi][0] = __float_as_uint(Ab[r * 36 + k0 + tig]);
                a[mi][1] = __float_as_uint(Ab[(r + 8) * 36 + k0 + tig]);
                a[mi][2] = __float_as_uint(Ab[r * 36 + k0 + tig + 4]);
                a[mi][3] = __float_as_uint(Ab[(r + 8) * 36 + k0 + tig + 4]);
            }
#pragma unroll
            for (int nj = 0; nj < 4; nj++) {
                int n0 = wn * 32 + nj * 8;
                uint32_t bb[2];
                bb[0] = __float_as_uint(Bb[(n0 + g) * 36 + k0 + tig]);
                bb[1] = __float_as_uint(Bb[(n0 + g) * 36 + k0 + tig + 4]);
#pragma unroll
                for (int mi = 0; mi < 4; mi++) mma16n8k8(acc[mi][nj], a[mi], bb);
            }
        }
    }

    // epilogue: m = global h row -> (step, batch); add bias; write logits
#pragma unroll
    for (int mi = 0; mi < 4; mi++) {
#pragma unroll
        for (int nj = 0; nj < 4; nj++) {
            int m0 = bm * 128 + wm * 64 + mi * 16 + g;
            int vv = bn * 128 + wn * 32 + nj * 8 + tig * 2;
            float b0 = bias[vv], b1 = bias[vv + 1];
            {
                int step = m0 >> 6, nn = m0 & 63;
                *(float2*)(out + ((long)nn * TT + step + 1) * VOC + vv) =
                    make_float2(acc[mi][nj][0] + b0, acc[mi][nj][1] + b1);
            }
            {
                int m1 = m0 + 8;
                int step = m1 >> 6, nn = m1 & 63;
                *(float2*)(out + ((long)nn * TT + step + 1) * VOC + vv) =
                    make_float2(acc[mi][nj][2] + b0, acc[mi][nj][3] + b1);
            }
        }
    }
}

// ---------------- launch ----------------
extern "C" void kernel_launch(void* const* d_in, const int* in_sizes, int n_in,
                              void* d_out, int out_size) {
    int sh = (n_in >= 19) ? 0 : 1;
    const float* keys     = (const float*)d_in[0];
    const float* values   = (const float*)d_in[1];
    const int*   captions = (const int*)d_in[3];
    const float* emb      = (const float*)d_in[5 - sh];
    const float* W_ih0    = (const float*)d_in[6 - sh];
    const float* W_hh0    = (const float*)d_in[7 - sh];
    const float* b_ih0    = (const float*)d_in[8 - sh];
    const float* b_hh0    = (const float*)d_in[9 - sh];
    const float* W_ih_r   = (const float*)d_in[10 - sh];
    const float* W_hh_r   = (const float*)d_in[11 - sh];
    const float* b_ih_r   = (const float*)d_in[12 - sh];
    const float* b_hh_r   = (const float*)d_in[13 - sh];
    const float* out_W    = (const float*)d_in[14 - sh];
    const float* out_b    = (const float*)d_in[15 - sh];
    const float* init_h   = (const float*)d_in[16 - sh];
    const float* init_c   = (const float*)d_in[17 - sh];
    const float* init_ctx = (const float*)d_in[18 - sh];
    float* out = (float*)d_out;

    cudaFuncSetAttribute(lstm_mma, cudaFuncAttributeMaxDynamicSharedMemorySize, LS_SMEM);
    cudaFuncSetAttribute(proj_mma, cudaFuncAttributeMaxDynamicSharedMemorySize, PJ_SMEM);

    init_state<<<768, 256>>>(init_h, init_c, init_ctx);
    out0_kernel<<<(NB * VOC + 255) / 256, 256>>>(out);
    embed_kernel<<<(NB * KX0 + 255) / 256, 256>>>(captions, emb, 0);

    for (int s = 0; s < NSTEP; s++) {
        lstm_mma<<<dim3(32, 5), 256, LS_SMEM>>>(0, W_ih0, W_hh0, KX0);
        gate_kernel<<<(NB * DEC + 255) / 256, 256>>>(0, b_ih0, b_hh0, 5, s);

        lstm_mma<<<dim3(32, 4), 256, LS_SMEM>>>(1, W_ih_r, W_hh_r, DEC);
        gate_kernel<<<(NB * DEC + 255) / 256, 256>>>(1, b_ih_r, b_hh_r, 4, s);

        lstm_mma<<<dim3(32, 4), 256, LS_SMEM>>>(2, W_ih_r + (long)G4 * DEC,
                                                W_hh_r + (long)G4 * DEC, DEC);
        gate_kernel<<<(NB * DEC + 255) / 256, 256>>>(2, b_ih_r + G4, b_hh_r + G4, 4, s);

        attn_kernel<<<NB, 256>>>(keys, values, captions, emb, s + 1);
    }

    proj_mma<<<dim3(VOC / 128, NSTEP * NB / 128), 256, PJ_SMEM>>>(out_W, out_b, out);
}

// round 8
// speedup vs baseline: 2.7969x; 1.7825x over previous
#include <cuda_runtime.h>
#include <cuda_bf16.h>
#include <stdint.h>

#define NB 64
#define TT 25
#define LL 196
#define VOC 32000
#define EMB 512
#define PROJD 1024
#define DEC 1024
#define G4 4096
#define NSTEP 24

// ---------------- device state (no allocations allowed) ----------------
__device__ __nv_bfloat16 d_wcat0[4096 * 2560];      // [Wih0 | Whh0] rows x K
__device__ __nv_bfloat16 d_wcat12[2][4096 * 2048];  // layers 1,2: [Wih | Whh]
__device__ __nv_bfloat16 d_pw[(long)VOC * DEC];     // out_W bf16
__device__ __nv_bfloat16 d_kbf[(long)NB * LL * DEC];
__device__ __nv_bfloat16 d_vbf[(long)NB * LL * PROJD];
__device__ __nv_bfloat16 d_xc0[NB * 2560];          // [emb | ctx | h0]
__device__ __nv_bfloat16 d_xc1[NB * 2048];          // [h0_new | h1]
__device__ __nv_bfloat16 d_xc2[NB * 2048];          // [h1_new | h2]
__device__ __nv_bfloat16 d_hlastb[(long)NSTEP * NB * DEC];
__device__ float d_gpart[5][NB * G4];
__device__ float d_cbuf[3][NB * DEC];
__device__ float d_h2[NB * DEC];
__device__ float d_att[NB * LL];

__device__ __forceinline__ float sigmf(float x) { return 1.0f / (1.0f + expf(-x)); }

__device__ __forceinline__ uint32_t smem_u32(const void* p) {
    uint32_t a;
    asm("{ .reg .u64 t; cvta.to.shared.u64 t, %1; cvt.u32.u64 %0, t; }" : "=r"(a) : "l"(p));
    return a;
}
#define CPA16(d, s) asm volatile("cp.async.ca.shared.global [%0], [%1], 16;" :: "r"(d), "l"(s))
#define CP_COMMIT() asm volatile("cp.async.commit_group;" ::: "memory")
#define CP_WAIT2() asm volatile("cp.async.wait_group 2;" ::: "memory")
#define CP_WAIT1() asm volatile("cp.async.wait_group 1;" ::: "memory")
#define CP_WAIT0() asm volatile("cp.async.wait_group 0;" ::: "memory")

// C[16x8] += A[16x16] * B[16x8], bf16 inputs, fp32 accum
__device__ __forceinline__ void mma_bf16(float* c, const uint32_t* a, uint32_t b0, uint32_t b1) {
    asm volatile(
        "mma.sync.aligned.m16n8k16.row.col.f32.bf16.bf16.f32 "
        "{%0,%1,%2,%3}, {%4,%5,%6,%7}, {%8,%9}, {%0,%1,%2,%3};"
        : "+f"(c[0]), "+f"(c[1]), "+f"(c[2]), "+f"(c[3])
        : "r"(a[0]), "r"(a[1]), "r"(a[2]), "r"(a[3]), "r"(b0), "r"(b1));
}

// ---------------- one-time conversions: fp32 -> bf16 (concat K of two sources) ----------------
__device__ __nv_bfloat16* conv_dst(int sel) {
    switch (sel) {
        case 0: return d_wcat0;
        case 1: return d_wcat12[0];
        case 2: return d_wcat12[1];
        case 3: return d_pw;
        case 4: return d_kbf;
        default: return d_vbf;
    }
}
__global__ void cat_bf16(const float4* __restrict__ A, int ka4, const float4* __restrict__ B,
                         int kb4, int sel, long total4) {
    __nv_bfloat16* dst = conv_dst(sel);
    int kt = ka4 + kb4;
    for (long i = (long)blockIdx.x * blockDim.x + threadIdx.x; i < total4;
         i += (long)gridDim.x * blockDim.x) {
        long row = i / kt;
        int k4 = (int)(i - row * kt);
        float4 v = (k4 < ka4) ? A[row * ka4 + k4] : B[row * kb4 + (k4 - ka4)];
        __nv_bfloat162* d2 = (__nv_bfloat162*)(dst + i * 4);
        d2[0] = __nv_bfloat162(__float2bfloat16_rn(v.x), __float2bfloat16_rn(v.y));
        d2[1] = __nv_bfloat162(__float2bfloat16_rn(v.z), __float2bfloat16_rn(v.w));
    }
}

// ---------------- init ----------------
__global__ void init_state(const float* __restrict__ ih, const float* __restrict__ ic,
                           const float* __restrict__ ictx, const float* __restrict__ emb) {
    int idx = blockIdx.x * blockDim.x + threadIdx.x;
    if (idx >= NB * 2560) return;
    int n = idx / 2560, j = idx % 2560;
    __nv_bfloat16 bv;
    if (j < 512) bv = __float2bfloat16_rn(emb[512 + j]);       // <start>=token 1
    else if (j < 1536) bv = __float2bfloat16_rn(ictx[j - 512]);
    else bv = __float2bfloat16_rn(ih[j - 1536]);
    d_xc0[idx] = bv;
    if (j < 1024) {
        d_xc1[n * 2048 + 1024 + j] = __float2bfloat16_rn(ih[1024 + j]);
        d_xc2[n * 2048 + 1024 + j] = __float2bfloat16_rn(ih[2048 + j]);
        d_cbuf[0][n * 1024 + j] = ic[j];
        d_cbuf[1][n * 1024 + j] = ic[1024 + j];
        d_cbuf[2][n * 1024 + j] = ic[2048 + j];
        d_h2[n * 1024 + j] = ih[2048 + j];
    }
}

__global__ void out0_kernel(float* __restrict__ out) {
    int idx = blockIdx.x * blockDim.x + threadIdx.x;
    if (idx < NB * VOC) {
        int n = idx / VOC, v = idx % VOC;
        out[(long)n * TT * VOC + v] = (v == 1) ? 10000.0f : 0.0f;
    }
}

// ---------------- LSTM GEMM (bf16 mma, 4-stage cp.async) ----------------
// g[64 x 4096] = X[64 x Ktot] @ W[4096 x Ktot]^T, split-K 512/CTA (16 chunks of 32).
// grid (64, KS), 128 threads. CTA tile 64(batch) x 64(W rows).
// stage: X 64 rows x 32 halves (stride 40) = 5120B, W same = 5120B.
#define LSTAGE 10240
#define LS_SMEM (4 * LSTAGE)

template <int LAYER>
__device__ __forceinline__ void lstm_ld(uint32_t st, int Ktot, int k0, int bn, int tid) {
    const __nv_bfloat16* Xc = (LAYER == 0) ? d_xc0 : (LAYER == 1) ? d_xc1 : d_xc2;
    const __nv_bfloat16* Wc = (LAYER == 0) ? d_wcat0 : d_wcat12[LAYER - 1];
#pragma unroll
    for (int i = 0; i < 2; i++) {
        int gI = tid + i * 128;
        int row = gI >> 2, c = gI & 3;
        CPA16(st + row * 80 + c * 16, Xc + (long)row * Ktot + k0 + c * 8);
    }
#pragma unroll
    for (int i = 0; i < 2; i++) {
        int gI = tid + i * 128;
        int row = gI >> 2, c = gI & 3;
        CPA16(st + 5120 + row * 80 + c * 16, Wc + (long)(bn * 64 + row) * Ktot + k0 + c * 8);
    }
}

template <int LAYER>
__global__ __launch_bounds__(128) void lstm_mma() {
    extern __shared__ char smem[];
    uint32_t sb = smem_u32(smem);
    const int Ktot = (LAYER == 0) ? 2560 : 2048;
    const int tid = threadIdx.x;
    const int w = tid >> 5, lane = tid & 31, g = lane >> 2, tig = lane & 3;
    const int bn = blockIdx.x;
    const int kbeg = blockIdx.y * 512;

    float acc[8][4] = {};

    lstm_ld<LAYER>(sb, Ktot, kbeg, bn, tid); CP_COMMIT();
    lstm_ld<LAYER>(sb + LSTAGE, Ktot, kbeg + 32, bn, tid); CP_COMMIT();
    lstm_ld<LAYER>(sb + 2 * LSTAGE, Ktot, kbeg + 64, bn, tid); CP_COMMIT();

    for (int c = 0; c < 16; c++) {
        if (c + 2 < 16) CP_WAIT2();
        else if (c + 1 < 16) CP_WAIT1();
        else CP_WAIT0();
        __syncthreads();
        if (c + 3 < 16) {
            lstm_ld<LAYER>(sb + ((c + 3) & 3) * LSTAGE, Ktot, kbeg + (c + 3) * 32, bn, tid);
            CP_COMMIT();
        }
        const uint32_t* Xu = (const uint32_t*)(smem + (c & 3) * LSTAGE);
        const uint32_t* Wu = (const uint32_t*)(smem + (c & 3) * LSTAGE + 5120);
        int m0g = (w * 16 + g) * 20;
#pragma unroll
        for (int ks = 0; ks < 2; ks++) {
            int k8 = ks * 8;
            uint32_t a[4];
            a[0] = Xu[m0g + k8 + tig];
            a[1] = Xu[m0g + 160 + k8 + tig];
            a[2] = Xu[m0g + k8 + tig + 4];
            a[3] = Xu[m0g + 160 + k8 + tig + 4];
#pragma unroll
            for (int nf = 0; nf < 8; nf++) {
                int nr = (nf * 8 + g) * 20;
                mma_bf16(acc[nf], a, Wu[nr + k8 + tig], Wu[nr + k8 + tig + 4]);
            }
        }
    }

    float* gp = d_gpart[blockIdx.y];
    int m = w * 16 + g;
#pragma unroll
    for (int nf = 0; nf < 8; nf++) {
        int coln = bn * 64 + nf * 8 + tig * 2;
        *(float2*)(gp + (long)m * G4 + coln) = make_float2(acc[nf][0], acc[nf][1]);
        *(float2*)(gp + (long)(m + 8) * G4 + coln) = make_float2(acc[nf][2], acc[nf][3]);
    }
}

// ---------------- gates: reduce split-K partials + biases, write bf16 h copies ----------------
__global__ void gate_kernel(int layer, const float* __restrict__ bih,
                            const float* __restrict__ bhh, int ks, int step) {
    int idx = blockIdx.x * blockDim.x + threadIdx.x;
    if (idx >= NB * DEC) return;
    int n = idx / DEC, j = idx % DEC;
    float gv[4];
#pragma unroll
    for (int q = 0; q < 4; q++) {
        int jj = q * DEC + j;
        float v = bih[jj] + bhh[jj];
        for (int s = 0; s < ks; s++) v += d_gpart[s][(long)n * G4 + jj];
        gv[q] = v;
    }
    float i_ = sigmf(gv[0]);
    float f_ = sigmf(gv[1]);
    float g_ = tanhf(gv[2]);
    float o_ = sigmf(gv[3]);
    float c2 = f_ * d_cbuf[layer][idx] + i_ * g_;
    float h2 = o_ * tanhf(c2);
    d_cbuf[layer][idx] = c2;
    __nv_bfloat16 hb = __float2bfloat16_rn(h2);
    if (layer == 0) {
        d_xc1[n * 2048 + j] = hb;                 // input to layer1 this step
        d_xc0[n * 2560 + 1536 + j] = hb;          // h0 for next step's layer0
    } else if (layer == 1) {
        d_xc2[n * 2048 + j] = hb;                 // input to layer2 this step
        d_xc1[n * 2048 + 1024 + j] = hb;          // h1 for next step
    } else {
        d_xc2[n * 2048 + 1024 + j] = hb;          // h2 for next step
        d_h2[idx] = h2;                           // fp32 for attention
        d_hlastb[((long)step * NB + n) * 1024 + j] = hb;
    }
}

// ---------------- attention part 1: energy = keys . h2 (bf16 keys) ----------------
// grid (64, 25), 256 threads, warp per row
__global__ void energy_kernel() {
    int n = blockIdx.x;
    int l = blockIdx.y * 8 + (threadIdx.x >> 5);
    int lane = threadIdx.x & 31;
    __shared__ float hs[DEC];
    for (int k = threadIdx.x; k < DEC; k += 256) hs[k] = d_h2[n * DEC + k];
    __syncthreads();
    if (l >= LL) return;
    const __nv_bfloat162* kr = (const __nv_bfloat162*)(d_kbf + ((long)n * LL + l) * DEC);
    float s = 0.f;
#pragma unroll
    for (int i = 0; i < 16; i++) {
        __nv_bfloat162 v = kr[lane + i * 32];
        int k2 = (lane + i * 32) * 2;
        s += __bfloat162float(v.x) * hs[k2] + __bfloat162float(v.y) * hs[k2 + 1];
    }
#pragma unroll
    for (int o = 16; o; o >>= 1) s += __shfl_xor_sync(0xffffffffu, s, o);
    if (lane == 0) d_att[n * LL + l] = s;
}

// ---------------- attention part 2: softmax + ctx + x0 build for next step ----------------
// grid (64, 4), 256 threads
__global__ void softctx_kernel(const int* __restrict__ captions, const float* __restrict__ emb,
                               int next_step) {
    int n = blockIdx.x;
    int tid = threadIdx.x;
    int wid = tid >> 5, lane = tid & 31;
    __shared__ float e[LL];
    __shared__ float red[8], red2[8];
    float v = (tid < LL) ? d_att[n * LL + tid] : -3.4e38f;
    float m = v;
#pragma unroll
    for (int o = 16; o; o >>= 1) m = fmaxf(m, __shfl_xor_sync(0xffffffffu, m, o));
    if (lane == 0) red[wid] = m;
    __syncthreads();
    if (tid < 8) {
        float mm = red[tid];
#pragma unroll
        for (int o = 4; o; o >>= 1) mm = fmaxf(mm, __shfl_xor_sync(0xffu, mm, o));
        if (tid == 0) red[0] = mm;
    }
    __syncthreads();
    float gm = red[0];
    float ex = (tid < LL) ? expf(v - gm) : 0.f;
    float s = ex;
#pragma unroll
    for (int o = 16; o; o >>= 1) s += __shfl_xor_sync(0xffffffffu, s, o);
    if (lane == 0) red2[wid] = s;
    __syncthreads();
    if (tid < 8) {
        float ss = red2[tid];
#pragma unroll
        for (int o = 4; o; o >>= 1) ss += __shfl_xor_sync(0xffu, ss, o);
        if (tid == 0) red2[0] = ss;
    }
    __syncthreads();
    if (tid < LL) e[tid] = ex / red2[0];
    __syncthreads();
    int col = blockIdx.y * 256 + tid;
    const __nv_bfloat16* vp = d_vbf + (long)n * LL * PROJD + col;
    float acc = 0.f;
#pragma unroll 4
    for (int l = 0; l < LL; l++) acc += e[l] * __bfloat162float(vp[(long)l * PROJD]);
    d_xc0[n * 2560 + 512 + col] = __float2bfloat16_rn(acc);
    if (blockIdx.y == 0) {
        int tok = captions[n * TT + next_step];
        for (int k = tid; k < EMB; k += 256)
            d_xc0[n * 2560 + k] = __float2bfloat16_rn(emb[(long)tok * EMB + k]);
    }
}

// ---------------- projection (bf16 mma, 4-stage): out = hlast @ out_W^T ----------------
// grid (12=bm, 250=bn) -> consecutive CTAs share the W tile via L2.
// CTA tile 128(h rows) x 128(vocab), K=1024 (32 chunks of 32).
#define PSTAGE 20480
#define PJ_SMEM (4 * PSTAGE)

__device__ __forceinline__ void proj_ld(uint32_t st, int bm, int bn, int k0, int tid) {
#pragma unroll
    for (int i = 0; i < 2; i++) {
        int gI = tid + i * 256;
        int row = gI >> 2, c = gI & 3;
        CPA16(st + row * 80 + c * 16, d_hlastb + (long)(bm * 128 + row) * DEC + k0 + c * 8);
    }
#pragma unroll
    for (int i = 0; i < 2; i++) {
        int gI = tid + i * 256;
        int row = gI >> 2, c = gI & 3;
        CPA16(st + 10240 + row * 80 + c * 16, d_pw + (long)(bn * 128 + row) * DEC + k0 + c * 8);
    }
}

__global__ __launch_bounds__(256) void proj_mma(const float* __restrict__ bias,
                                                float* __restrict__ out) {
    extern __shared__ char smem[];
    uint32_t sb = smem_u32(smem);
    const int tid = threadIdx.x;
    const int w = tid >> 5, lane = tid & 31, g = lane >> 2, tig = lane & 3;
    const int wm = w >> 2, wn = w & 3;  // warp tile rows wm*64, cols wn*32
    const int bm = blockIdx.x, bn = blockIdx.y;

    float acc[4][4][4] = {};

    proj_ld(sb, bm, bn, 0, tid); CP_COMMIT();
    proj_ld(sb + PSTAGE, bm, bn, 32, tid); CP_COMMIT();
    proj_ld(sb + 2 * PSTAGE, bm, bn, 64, tid); CP_COMMIT();

    for (int c = 0; c < 32; c++) {
        if (c + 2 < 32) CP_WAIT2();
        else if (c + 1 < 32) CP_WAIT1();
        else CP_WAIT0();
        __syncthreads();
        if (c + 3 < 32) {
            proj_ld(sb + ((c + 3) & 3) * PSTAGE, bm, bn, (c + 3) * 32, tid);
            CP_COMMIT();
        }
        const uint32_t* Au = (const uint32_t*)(smem + (c & 3) * PSTAGE);
        const uint32_t* Bu = (const uint32_t*)(smem + (c & 3) * PSTAGE + 10240);
#pragma unroll
        for (int ks = 0; ks < 2; ks++) {
            int k8 = ks * 8;
            uint32_t a[4][4];
#pragma unroll
            for (int mi = 0; mi < 4; mi++) {
                int r = (wm * 64 + mi * 16 + g) * 20;
                a[mi][0] = Au[r + k8 + tig];
                a[mi][1] = Au[r + 160 + k8 + tig];
                a[mi][2] = Au[r + k8 + tig + 4];
                a[mi][3] = Au[r + 160 + k8 + tig + 4];
            }
#pragma unroll
            for (int nj = 0; nj < 4; nj++) {
                int nr = (wn * 32 + nj * 8 + g) * 20;
                uint32_t b0 = Bu[nr + k8 + tig], b1 = Bu[nr + k8 + tig + 4];
#pragma unroll
                for (int mi = 0; mi < 4; mi++) mma_bf16(acc[mi][nj], a[mi], b0, b1);
            }
        }
    }

#pragma unroll
    for (int mi = 0; mi < 4; mi++) {
#pragma unroll
        for (int nj = 0; nj < 4; nj++) {
            int m0 = bm * 128 + wm * 64 + mi * 16 + g;
            int vv = bn * 128 + wn * 32 + nj * 8 + tig * 2;
            float b0 = bias[vv], b1 = bias[vv + 1];
            {
                int step = m0 >> 6, nn = m0 & 63;
                *(float2*)(out + ((long)nn * TT + step + 1) * VOC + vv) =
                    make_float2(acc[mi][nj][0] + b0, acc[mi][nj][1] + b1);
            }
            {
                int m1 = m0 + 8;
                int step = m1 >> 6, nn = m1 & 63;
                *(float2*)(out + ((long)nn * TT + step + 1) * VOC + vv) =
                    make_float2(acc[mi][nj][2] + b0, acc[mi][nj][3] + b1);
            }
        }
    }
}

// ---------------- launch ----------------
extern "C" void kernel_launch(void* const* d_in, const int* in_sizes, int n_in,
                              void* d_out, int out_size) {
    int sh = (n_in >= 19) ? 0 : 1;
    const float* keys     = (const float*)d_in[0];
    const float* values   = (const float*)d_in[1];
    const int*   captions = (const int*)d_in[3];
    const float* emb      = (const float*)d_in[5 - sh];
    const float* W_ih0    = (const float*)d_in[6 - sh];
    const float* W_hh0    = (const float*)d_in[7 - sh];
    const float* b_ih0    = (const float*)d_in[8 - sh];
    const float* b_hh0    = (const float*)d_in[9 - sh];
    const float* W_ih_r   = (const float*)d_in[10 - sh];
    const float* W_hh_r   = (const float*)d_in[11 - sh];
    const float* b_ih_r   = (const float*)d_in[12 - sh];
    const float* b_hh_r   = (const float*)d_in[13 - sh];
    const float* out_W    = (const float*)d_in[14 - sh];
    const float* out_b    = (const float*)d_in[15 - sh];
    const float* init_h   = (const float*)d_in[16 - sh];
    const float* init_c   = (const float*)d_in[17 - sh];
    const float* init_ctx = (const float*)d_in[18 - sh];
    float* out = (float*)d_out;

    cudaFuncSetAttribute(lstm_mma<0>, cudaFuncAttributeMaxDynamicSharedMemorySize, LS_SMEM);
    cudaFuncSetAttribute(lstm_mma<1>, cudaFuncAttributeMaxDynamicSharedMemorySize, LS_SMEM);
    cudaFuncSetAttribute(lstm_mma<2>, cudaFuncAttributeMaxDynamicSharedMemorySize, LS_SMEM);
    cudaFuncSetAttribute(proj_mma, cudaFuncAttributeMaxDynamicSharedMemorySize, PJ_SMEM);

    // one-time conversions (part of the graph; deterministic)
    cat_bf16<<<1024, 256>>>((const float4*)W_ih0, 384, (const float4*)W_hh0, 256, 0,
                            (long)4096 * 640);
    cat_bf16<<<1024, 256>>>((const float4*)W_ih_r, 256, (const float4*)W_hh_r, 256, 1,
                            (long)4096 * 512);
    cat_bf16<<<1024, 256>>>((const float4*)(W_ih_r + (long)4096 * 1024), 256,
                            (const float4*)(W_hh_r + (long)4096 * 1024), 256, 2,
                            (long)4096 * 512);
    cat_bf16<<<1024, 256>>>((const float4*)out_W, 256, (const float4*)out_W, 0, 3,
                            (long)VOC * 256);
    cat_bf16<<<1024, 256>>>((const float4*)keys, 256, (const float4*)keys, 0, 4,
                            (long)NB * LL * 256);
    cat_bf16<<<1024, 256>>>((const float4*)values, 256, (const float4*)values, 0, 5,
                            (long)NB * LL * 256);

    init_state<<<640, 256>>>(init_h, init_c, init_ctx, emb);
    out0_kernel<<<(NB * VOC + 255) / 256, 256>>>(out);

    for (int s = 0; s < NSTEP; s++) {
        lstm_mma<0><<<dim3(64, 5), 128, LS_SMEM>>>();
        gate_kernel<<<256, 256>>>(0, b_ih0, b_hh0, 5, s);

        lstm_mma<1><<<dim3(64, 4), 128, LS_SMEM>>>();
        gate_kernel<<<256, 256>>>(1, b_ih_r, b_hh_r, 4, s);

        lstm_mma<2><<<dim3(64, 4), 128, LS_SMEM>>>();
        gate_kernel<<<256, 256>>>(2, b_ih_r + G4, b_hh_r + G4, 4, s);

        energy_kernel<<<dim3(64, 25), 256>>>();
        softctx_kernel<<<dim3(64, 4), 256>>>(captions, emb, s + 1);
    }

    proj_mma<<<dim3(12, 250), 256, PJ_SMEM>>>(out_b, out);
}